// round 8
// baseline (speedup 1.0000x reference)
#include <cuda_runtime.h>
#include <cuda_bf16.h>
#include <stdint.h>

// RoIAlign: feat (B=4, C=256, H=200, W=304) fp32, rois (N,5) fp32
// OUT=7, SCALE=0.25, sampling_ratio=1, aligned=False
// out: (N, C, 7, 7) fp32

#define B_ 4
#define C_ 256
#define H_ 200
#define W_ 304
#define OUT_ 7
#define BINS_PER_ROI (OUT_ * OUT_)      // 49
#define HW_ (H_ * W_)                   // 60800  (== 0 mod 4)
#define CHW_ (C_ * HW_)                 // 15,564,800 (== 0 mod 4)
#define SCALE_ 0.25f

#define CG_ 32                          // channels per gather block
#define NCG_ (C_ / CG_)                 // 8 channel groups
#define GATHER_THREADS 224              // 1568 elems / 7 per thread, exact
#define ELEMS_PER_THREAD 7

#define MAX_ROIS 8192
// Per-bin metadata. g_off low 2 bits carry r = x0 & 3 (all other address
// terms are ==0 mod 4 since W, HW, CHW are multiples of 4).
__device__ int    g_off[MAX_ROIS * BINS_PER_ROI];   // b*CHW + y0*W + x0
__device__ float4 g_wa[MAX_ROIS * BINS_PER_ROI];    // row0 float4 dot-mask
__device__ float4 g_wb[MAX_ROIS * BINS_PER_ROI];    // row1 float4 dot-mask
__device__ float2 g_we[MAX_ROIS * BINS_PER_ROI];    // r==3 spill weights
__device__ int    g_order[MAX_ROIS];                // rois sorted by batch

// ---------------------------------------------------------------------------
// Fused phase 1: blocks [0, gridDim-2] do per-(roi,bin) prep; the last block
// does a 4-bucket counting sort of rois by batch id (runs concurrently —
// prep and sort touch disjoint arrays; gather depends on both).
// ---------------------------------------------------------------------------
__global__ __launch_bounds__(256)
void roi_prep_sort_kernel(const float* __restrict__ rois,
                          int n_bins, int n_rois) {
    int tid = threadIdx.x;

    if (blockIdx.x == gridDim.x - 1) {
        // ---- sort path (order within bucket irrelevant: each roi writes a
        // disjoint output slice, so atomic scatter is deterministic-safe) ----
        __shared__ int s_count[B_];
        __shared__ int s_base[B_];
        __shared__ int s_pos[B_];

        if (tid < B_) s_count[tid] = 0;
        __syncthreads();

        for (int n = tid; n < n_rois; n += 256)
            atomicAdd(&s_count[(int)rois[n * 5]], 1);
        __syncthreads();

        if (tid == 0) {
            int acc = 0;
            for (int b = 0; b < B_; b++) { s_base[b] = acc; acc += s_count[b]; s_pos[b] = 0; }
        }
        __syncthreads();

        for (int n = tid; n < n_rois; n += 256) {
            int b = (int)rois[n * 5];
            int pos = s_base[b] + atomicAdd(&s_pos[b], 1);
            g_order[pos] = n;
        }
        return;
    }

    // ---- prep path ----
    int i = blockIdx.x * 256 + tid;
    if (i >= n_bins) return;

    int n  = i / BINS_PER_ROI;
    int p  = i - n * BINS_PER_ROI;
    int ph = p / OUT_;
    int pw = p - ph * OUT_;

    const float* r = rois + n * 5;
    int   b   = (int)r[0];
    float sx1 = r[1] * SCALE_;
    float sy1 = r[2] * SCALE_;
    float sx2 = r[3] * SCALE_;
    float sy2 = r[4] * SCALE_;

    float rw = fmaxf(sx2 - sx1, 1.0f);   // aligned=False -> clamp to 1
    float rh = fmaxf(sy2 - sy1, 1.0f);
    float bin_w = rw * (1.0f / OUT_);
    float bin_h = rh * (1.0f / OUT_);

    // sampling_ratio = 1: single sample at bin center
    float x = sx1 + ((float)pw + 0.5f) * bin_w;
    float y = sy1 + ((float)ph + 0.5f) * bin_h;

    float valid = (y > -1.0f && y < (float)H_ && x > -1.0f && x < (float)W_)
                      ? 1.0f : 0.0f;

    y = fminf(fmaxf(y, 0.0f), (float)(H_ - 1));
    x = fminf(fmaxf(x, 0.0f), (float)(W_ - 1));

    int   y0 = (int)floorf(y);
    int   x0 = (int)floorf(x);
    float ly = y - (float)y0;
    float lx = x - (float)x0;

    // Edge re-parameterization: keep (y0+1, x0+1) taps in-bounds.
    if (y0 >= H_ - 1) { y0 = H_ - 2; ly = 1.0f; }
    if (x0 >= W_ - 1) { x0 = W_ - 2; lx = 1.0f; }

    float hy = 1.0f - ly;
    float hx = 1.0f - lx;

    float hyhx = hy * hx * valid;
    float hylx = hy * lx * valid;
    float lyhx = ly * hx * valid;
    float lylx = ly * lx * valid;

    // Rotate weights into float4-aligned dot masks. rslot = x0 & 3: the tap
    // at x0 lands in slot rslot of the aligned float4; x0+1 in rslot+1
    // (or spills to the extra scalar when rslot == 3).
    int rslot = x0 & 3;
    float4 wa = make_float4(0.f, 0.f, 0.f, 0.f);
    float4 wb = make_float4(0.f, 0.f, 0.f, 0.f);
    float2 we = make_float2(0.f, 0.f);
    switch (rslot) {
        case 0: wa.x = hyhx; wa.y = hylx; wb.x = lyhx; wb.y = lylx; break;
        case 1: wa.y = hyhx; wa.z = hylx; wb.y = lyhx; wb.z = lylx; break;
        case 2: wa.z = hyhx; wa.w = hylx; wb.z = lyhx; wb.w = lylx; break;
        default: wa.w = hyhx; wb.w = lyhx; we.x = hylx; we.y = lylx; break;
    }

    g_off[i] = b * CHW_ + y0 * W_ + x0;
    g_wa[i]  = wa;
    g_wb[i]  = wb;
    g_we[i]  = we;
}

// ---------------------------------------------------------------------------
// Phase 2: one block = (batch-sorted roi slot, 32-channel group).
// Bin metadata staged in smem once per block. Per element: two float4 loads
// cover both horizontal tap pairs (W, HW, CHW all ==0 mod 4 so the aligned
// float4 never crosses a row -> always in-bounds); r==3 bins (25%) take two
// extra predicated scalar loads. This halves L1tex wavefronts vs 4 scalar
// taps. Stores are fully coalesced (contiguous 1568-float slice per block).
// ---------------------------------------------------------------------------
__global__ __launch_bounds__(GATHER_THREADS)
void roi_gather_kernel(const float* __restrict__ feat,
                       float* __restrict__ out) {
    __shared__ int    s_off[BINS_PER_ROI];
    __shared__ float4 s_wa[BINS_PER_ROI];
    __shared__ float4 s_wb[BINS_PER_ROI];
    __shared__ float2 s_we[BINS_PER_ROI];

    int slot = blockIdx.x >> 3;          // / NCG_ (8)
    int cg   = blockIdx.x & (NCG_ - 1);
    int n    = g_order[slot];
    int c0   = cg * CG_;

    int tid = threadIdx.x;
    if (tid < BINS_PER_ROI) {
        int bin = n * BINS_PER_ROI + tid;
        s_off[tid] = g_off[bin];
        s_wa[tid]  = g_wa[bin];
        s_wb[tid]  = g_wb[bin];
        s_we[tid]  = g_we[bin];
    }
    __syncthreads();

    float* out_base = out + (n * C_ + c0) * BINS_PER_ROI;

    #pragma unroll
    for (int i = 0; i < ELEMS_PER_THREAD; i++) {
        int idx = tid + i * GATHER_THREADS;
        int c   = idx / BINS_PER_ROI;
        int p   = idx - c * BINS_PER_ROI;

        int off = s_off[p] + (c0 + c) * HW_;
        int a   = off & ~3;

        const float4* base = (const float4*)(feat + a);
        float4 t0 = __ldg(base);
        float4 t1 = __ldg(base + (W_ / 4));

        float4 wa = s_wa[p];
        float4 wb = s_wb[p];

        float acc = t0.x * wa.x + t0.y * wa.y + t0.z * wa.z + t0.w * wa.w
                  + t1.x * wb.x + t1.y * wb.y + t1.z * wb.z + t1.w * wb.w;

        if ((off & 3) == 3) {
            float2 we = s_we[p];
            float e0 = __ldg(feat + off + 1);
            float e1 = __ldg(feat + off + 1 + W_);
            acc += e0 * we.x + e1 * we.y;
        }

        out_base[idx] = acc;
    }
}

// ---------------------------------------------------------------------------
extern "C" void kernel_launch(void* const* d_in, const int* in_sizes, int n_in,
                              void* d_out, int out_size) {
    const float* feat = (const float*)d_in[0];
    const float* rois = (const float*)d_in[1];
    float* out = (float*)d_out;

    int N = in_sizes[1] / 5;
    int n_bins = N * BINS_PER_ROI;
    int prep_blocks = (n_bins + 255) / 256;

    roi_prep_sort_kernel<<<prep_blocks + 1, 256>>>(rois, n_bins, N);
    roi_gather_kernel<<<N * NCG_, GATHER_THREADS>>>(feat, out);
}

// round 11
// speedup vs baseline: 1.2980x; 1.2980x over previous
#include <cuda_runtime.h>
#include <cuda_bf16.h>
#include <stdint.h>

// RoIAlign: feat (B=4, C=256, H=200, W=304) fp32, rois (N,5) fp32
// OUT=7, SCALE=0.25, sampling_ratio=1, aligned=False
// out: (N, C, 7, 7) fp32

#define B_ 4
#define C_ 256
#define H_ 200
#define W_ 304
#define OUT_ 7
#define BINS_PER_ROI (OUT_ * OUT_)      // 49
#define HW_ (H_ * W_)                   // 60800
#define CHW_ (C_ * HW_)                 // 15,564,800
#define SCALE_ 0.25f

#define CG_ 32                          // channels per gather block
#define NCG_ (C_ / CG_)                 // 8 channel groups
#define GATHER_THREADS 196              // 4 groups x 49 bins
#define CH_PER_THREAD 8                 // 196 * 8 = 1568 = CG_ * 49 exactly

#define MAX_ROIS 8192
__device__ int    g_off[MAX_ROIS * BINS_PER_ROI];   // b*CHW + y0*W + x0
__device__ float4 g_w[MAX_ROIS * BINS_PER_ROI];     // bilinear weights * valid
__device__ int    g_order[MAX_ROIS];                // rois sorted by batch

// ---------------------------------------------------------------------------
// Fused phase 1: blocks [0, gridDim-2] do per-(roi,bin) prep; the last block
// does a 4-bucket counting sort of rois by batch id (concurrent: disjoint
// outputs; gather depends on both).
// ---------------------------------------------------------------------------
__global__ __launch_bounds__(256)
void roi_prep_sort_kernel(const float* __restrict__ rois,
                          int n_bins, int n_rois) {
    int tid = threadIdx.x;

    if (blockIdx.x == gridDim.x - 1) {
        // ---- sort path (order within bucket irrelevant: each roi writes a
        // disjoint output slice, so atomic scatter is deterministic-safe) ----
        __shared__ int s_count[B_];
        __shared__ int s_base[B_];
        __shared__ int s_pos[B_];

        if (tid < B_) s_count[tid] = 0;
        __syncthreads();

        for (int n = tid; n < n_rois; n += 256)
            atomicAdd(&s_count[(int)rois[n * 5]], 1);
        __syncthreads();

        if (tid == 0) {
            int acc = 0;
            for (int b = 0; b < B_; b++) { s_base[b] = acc; acc += s_count[b]; s_pos[b] = 0; }
        }
        __syncthreads();

        for (int n = tid; n < n_rois; n += 256) {
            int b = (int)rois[n * 5];
            int pos = s_base[b] + atomicAdd(&s_pos[b], 1);
            g_order[pos] = n;
        }
        return;
    }

    // ---- prep path ----
    int i = blockIdx.x * 256 + tid;
    if (i >= n_bins) return;

    int n  = i / BINS_PER_ROI;
    int p  = i - n * BINS_PER_ROI;
    int ph = p / OUT_;
    int pw = p - ph * OUT_;

    const float* r = rois + n * 5;
    int   b   = (int)r[0];
    float sx1 = r[1] * SCALE_;
    float sy1 = r[2] * SCALE_;
    float sx2 = r[3] * SCALE_;
    float sy2 = r[4] * SCALE_;

    float rw = fmaxf(sx2 - sx1, 1.0f);   // aligned=False -> clamp to 1
    float rh = fmaxf(sy2 - sy1, 1.0f);
    float bin_w = rw * (1.0f / OUT_);
    float bin_h = rh * (1.0f / OUT_);

    // sampling_ratio = 1: single sample at bin center
    float x = sx1 + ((float)pw + 0.5f) * bin_w;
    float y = sy1 + ((float)ph + 0.5f) * bin_h;

    float valid = (y > -1.0f && y < (float)H_ && x > -1.0f && x < (float)W_)
                      ? 1.0f : 0.0f;

    y = fminf(fmaxf(y, 0.0f), (float)(H_ - 1));
    x = fminf(fmaxf(x, 0.0f), (float)(W_ - 1));

    int   y0 = (int)floorf(y);
    int   x0 = (int)floorf(x);
    float ly = y - (float)y0;
    float lx = x - (float)x0;

    // Edge re-parameterization: keep (y0+1, x0+1) taps in-bounds.
    if (y0 >= H_ - 1) { y0 = H_ - 2; ly = 1.0f; }
    if (x0 >= W_ - 1) { x0 = W_ - 2; lx = 1.0f; }

    float hy = 1.0f - ly;
    float hx = 1.0f - lx;

    g_off[i] = b * CHW_ + y0 * W_ + x0;
    g_w[i]   = make_float4(hy * hx * valid,
                           hy * lx * valid,
                           ly * hx * valid,
                           ly * lx * valid);
}

// ---------------------------------------------------------------------------
// Phase 2: one block = (batch-sorted roi slot, 32-channel group).
// 196 threads = 4 groups x 49 bins. Each thread owns ONE bin: its metadata
// (offset + float4 weights) is loaded once into registers, then 8 channels
// are processed with 4 scalar taps + 1 coalesced store each. Zero shared
// memory in the hot loop -> l1tex bytes/element drop from ~40B to ~20B.
// Warp tap pattern: lanes span consecutive bins at fixed channel (the
// good-line-sharing layout from R4).
// ---------------------------------------------------------------------------
__global__ __launch_bounds__(GATHER_THREADS)
void roi_gather_kernel(const float* __restrict__ feat,
                       float* __restrict__ out) {
    int slot = blockIdx.x >> 3;          // / NCG_ (8)
    int cg   = blockIdx.x & (NCG_ - 1);
    int n    = g_order[slot];
    int c0   = cg * CG_;

    int t = threadIdx.x;
    int g = t / BINS_PER_ROI;            // 0..3
    int p = t - g * BINS_PER_ROI;        // 0..48

    int bin = n * BINS_PER_ROI + p;
    int    off_base = g_off[bin] + (c0 + g * CH_PER_THREAD) * HW_;
    float4 w        = g_w[bin];

    float* out_base = out + (n * C_ + c0 + g * CH_PER_THREAD) * BINS_PER_ROI + p;

    #pragma unroll
    for (int i = 0; i < CH_PER_THREAD; i++) {
        const float* ptr = feat + off_base + i * HW_;
        float f00 = __ldg(ptr);
        float f01 = __ldg(ptr + 1);
        float f10 = __ldg(ptr + W_);
        float f11 = __ldg(ptr + W_ + 1);

        out_base[i * BINS_PER_ROI] =
            f00 * w.x + f01 * w.y + f10 * w.z + f11 * w.w;
    }
}

// ---------------------------------------------------------------------------
extern "C" void kernel_launch(void* const* d_in, const int* in_sizes, int n_in,
                              void* d_out, int out_size) {
    const float* feat = (const float*)d_in[0];
    const float* rois = (const float*)d_in[1];
    float* out = (float*)d_out;

    int N = in_sizes[1] / 5;
    int n_bins = N * BINS_PER_ROI;
    int prep_blocks = (n_bins + 255) / 256;

    roi_prep_sort_kernel<<<prep_blocks + 1, 256>>>(rois, n_bins, N);
    roi_gather_kernel<<<N * NCG_, GATHER_THREADS>>>(feat, out);
}